// round 9
// baseline (speedup 1.0000x reference)
#include <cuda_runtime.h>
#include <math.h>
#include <cstdint>

// memory: [B=256, M=8192, W=32] f32 ; keys: [B,H=4,W=32] ; strengths: [B,H]
// out[b,h,m] = softmax_M( dot/(kn*mn+eps) * softplus(strength) )
// |cos|<1 -> v <= beta: softmax shifted by beta -> associative sum.
// 16 blocks per batch write e=exp(v-beta) + per-seg partial sums; the LAST
// block to finish a batch (ticket) sums the partials in fixed order and
// normalizes that batch's slice from L2 (dirty lines -> no DRAM double-write).

#define NB      256
#define MM      8192
#define WW      32
#define HH      4
#define EPSF    1e-5f
#define SPLITS  16
#define NT1     256
#define ROWS_PER_BLOCK (MM / SPLITS)                 // 512
#define NWARPS  (NT1 / 32)                           // 8
#define ROWS_PER_WARP  (ROWS_PER_BLOCK / NWARPS)     // 64
#define ITERS   (ROWS_PER_WARP / 8)                  // 8 (8 rows / warp-iter)

__device__ float    g_partial[NB * HH * SPLITS];
__device__ unsigned g_ticket[NB];                    // zero-initialized

// un-hoistable shared load: keeps key data out of the register file
__device__ __forceinline__ float4 lds128(uint32_t addr) {
    float4 v;
    asm volatile("ld.shared.v4.f32 {%0,%1,%2,%3}, [%4];"
        : "=f"(v.x), "=f"(v.y), "=f"(v.z), "=f"(v.w) : "r"(addr));
    return v;
}

__global__ __launch_bounds__(NT1, 6)
void weightfn_k1(const float* __restrict__ mem,
                 const float* __restrict__ keys,
                 const float* __restrict__ strengths,
                 float* __restrict__ out)
{
    __shared__ float4   sk4[HH][WW / 4];   // keys, [h][chunk]
    __shared__ float    skn[HH];
    __shared__ float    sbeta[HH];
    __shared__ float    sred[NWARPS][4];
    __shared__ unsigned sticket;
    __shared__ float    sinv[HH];

    const int bidx = blockIdx.x;
    const int b    = bidx >> 4;              // / SPLITS
    const int seg  = bidx & (SPLITS - 1);
    const int tid  = threadIdx.x;
    const int lane = tid & 31;
    const int wid  = tid >> 5;
    const int sub  = lane & 3;               // quarter of row / h index
    const int g    = lane >> 2;              // row within 8-row group

    if (tid < HH * WW)
        ((float*)sk4)[tid] = keys[b * HH * WW + tid];
    __syncthreads();
    if (tid < HH) {
        float s = strengths[b * HH + tid];
        sbeta[tid] = (s > 20.0f) ? s : log1pf(__expf(s));
        const float* k = (const float*)sk4[tid];
        float sq = 0.0f;
        #pragma unroll
        for (int w = 0; w < WW; w++) sq = fmaf(k[w], k[w], sq);
        skn[tid] = sqrtf(sq + EPSF);
    }
    __syncthreads();

    const float beta_h = sbeta[sub];
    const float kn_h   = skn[sub];

    // shared base address of this lane's key quarter: sk4[0][sub*2]
    const uint32_t skbase =
        (uint32_t)__cvta_generic_to_shared(&sk4[0][0]) + (uint32_t)(sub * 32);

    const float4* mp4 = (const float4*)mem + (size_t)b * MM * (WW / 4);
    float* ob = out + (size_t)b * HH * MM;

    const int warpRow0 = seg * ROWS_PER_BLOCK + wid * ROWS_PER_WARP;
    float lsum = 0.0f;

    #pragma unroll
    for (int i = 0; i < ITERS; i += 2) {
        const int rowA = warpRow0 + i * 8 + g;
        const int rowB = rowA + 8;
        // 4 LDG.128 front-batched (MLP 4)
        const float4 a0 = __ldcs(&mp4[rowA * 8 + sub * 2]);
        const float4 a1 = __ldcs(&mp4[rowA * 8 + sub * 2 + 1]);
        const float4 b0 = __ldcs(&mp4[rowB * 8 + sub * 2]);
        const float4 b1 = __ldcs(&mp4[rowB * 8 + sub * 2 + 1]);

        float sqA = fmaf(a0.x, a0.x, fmaf(a0.y, a0.y,
                    fmaf(a0.z, a0.z, fmaf(a0.w, a0.w, 0.0f))));
        sqA = fmaf(a1.x, a1.x, fmaf(a1.y, a1.y,
              fmaf(a1.z, a1.z, fmaf(a1.w, a1.w, sqA))));
        float sqB = fmaf(b0.x, b0.x, fmaf(b0.y, b0.y,
                    fmaf(b0.z, b0.z, fmaf(b0.w, b0.w, 0.0f))));
        sqB = fmaf(b1.x, b1.x, fmaf(b1.y, b1.y,
              fmaf(b1.z, b1.z, fmaf(b1.w, b1.w, sqB))));

        float dotA[HH], dotB[HH];
        #pragma unroll
        for (int h = 0; h < HH; h++) {
            const float4 k0 = lds128(skbase + (uint32_t)(h * 128));
            const float4 k1 = lds128(skbase + (uint32_t)(h * 128 + 16));
            float dA = fmaf(a0.x, k0.x, fmaf(a0.y, k0.y,
                       fmaf(a0.z, k0.z, fmaf(a0.w, k0.w, 0.0f))));
            dA = fmaf(a1.x, k1.x, fmaf(a1.y, k1.y,
                 fmaf(a1.z, k1.z, fmaf(a1.w, k1.w, dA))));
            float dB = fmaf(b0.x, k0.x, fmaf(b0.y, k0.y,
                       fmaf(b0.z, k0.z, fmaf(b0.w, k0.w, 0.0f))));
            dB = fmaf(b1.x, k1.x, fmaf(b1.y, k1.y,
                 fmaf(b1.z, k1.z, fmaf(b1.w, k1.w, dB))));
            dotA[h] = dA;
            dotB[h] = dB;
        }

        #pragma unroll
        for (int mask = 1; mask <= 2; mask <<= 1) {
            sqA += __shfl_xor_sync(0xffffffffu, sqA, mask);
            sqB += __shfl_xor_sync(0xffffffffu, sqB, mask);
            #pragma unroll
            for (int h = 0; h < HH; h++) {
                dotA[h] += __shfl_xor_sync(0xffffffffu, dotA[h], mask);
                dotB[h] += __shfl_xor_sync(0xffffffffu, dotB[h], mask);
            }
        }

        float dA = (sub == 0) ? dotA[0] : (sub == 1) ? dotA[1]
                 : (sub == 2) ? dotA[2] : dotA[3];
        float dB = (sub == 0) ? dotB[0] : (sub == 1) ? dotB[1]
                 : (sub == 2) ? dotB[2] : dotB[3];

        const float mnA = sqrtf(sqA + EPSF);
        const float mnB = sqrtf(sqB + EPSF);
        const float vA = dA * __fdividef(beta_h, fmaf(kn_h, mnA, EPSF));
        const float vB = dB * __fdividef(beta_h, fmaf(kn_h, mnB, EPSF));
        const float eA = __expf(vA - beta_h);
        const float eB = __expf(vB - beta_h);
        ob[sub * MM + rowA] = eA;
        ob[sub * MM + rowB] = eB;
        lsum += eA + eB;
    }

    // sum over 8 lanes sharing this sub (=h)
    #pragma unroll
    for (int mask = 4; mask <= 16; mask <<= 1)
        lsum += __shfl_xor_sync(0xffffffffu, lsum, mask);
    if (lane < 4) sred[wid][lane] = lsum;
    __syncthreads();

    if (tid < 32) {
        float v = sred[tid >> 2][tid & 3];   // 8 warps x 4 h
        #pragma unroll
        for (int mask = 4; mask <= 16; mask <<= 1)
            v += __shfl_xor_sync(0xffffffffu, v, mask);
        if (tid < 4)
            g_partial[(b * HH + tid) * SPLITS + seg] = v;
    }

    // ---- ticket: last block of this batch normalizes it ----
    __threadfence();                 // publish e-values + partials (gpu scope)
    __syncthreads();
    if (tid == 0) sticket = atomicAdd(&g_ticket[b], 1u);
    __syncthreads();
    if (sticket != SPLITS - 1) return;

    // finisher
    if (tid == 0) g_ticket[b] = 0;   // reset for next launch / graph replay
    __threadfence();                 // acquire: see all segs' writes

    if (tid < 64) {                  // 4 h x 16 segs, fixed-order pairwise sum
        float v = g_partial[(b * HH + (tid >> 4)) * SPLITS + (tid & 15)];
        #pragma unroll
        for (int m = 1; m <= 8; m <<= 1)
            v += __shfl_xor_sync(0xffffffffu, v, m);
        if ((tid & 15) == 0) sinv[tid >> 4] = __fdividef(1.0f, v);
    }
    __syncthreads();

    // normalize 8192 float4 with 256 threads; 4 loads in flight per step.
    // Within step k, all indices share the same h (= k>>1).
    float4* o4 = (float4*)ob;
    #pragma unroll
    for (int k = 0; k < 8; k++) {
        const float inv = sinv[k >> 1];
        const int i0 = tid + (k * 4 + 0) * 256;
        const int i1 = tid + (k * 4 + 1) * 256;
        const int i2 = tid + (k * 4 + 2) * 256;
        const int i3 = tid + (k * 4 + 3) * 256;
        float4 v0 = __ldcg(&o4[i0]);
        float4 v1 = __ldcg(&o4[i1]);
        float4 v2 = __ldcg(&o4[i2]);
        float4 v3 = __ldcg(&o4[i3]);
        v0.x *= inv; v0.y *= inv; v0.z *= inv; v0.w *= inv;
        v1.x *= inv; v1.y *= inv; v1.z *= inv; v1.w *= inv;
        v2.x *= inv; v2.y *= inv; v2.z *= inv; v2.w *= inv;
        v3.x *= inv; v3.y *= inv; v3.z *= inv; v3.w *= inv;
        __stcs(&o4[i0], v0);
        __stcs(&o4[i1], v1);
        __stcs(&o4[i2], v2);
        __stcs(&o4[i3], v3);
    }
}

extern "C" void kernel_launch(void* const* d_in, const int* in_sizes, int n_in,
                              void* d_out, int out_size)
{
    const float* mem       = (const float*)d_in[0];
    const float* keys      = (const float*)d_in[1];
    const float* strengths = (const float*)d_in[2];
    float* out             = (float*)d_out;

    weightfn_k1<<<NB * SPLITS, NT1>>>(mem, keys, strengths, out);
}

// round 10
// speedup vs baseline: 1.6297x; 1.6297x over previous
#include <cuda_runtime.h>
#include <math.h>
#include <cstdint>

// memory: [B=256, M=8192, W=32] f32 ; keys: [B,H=4,W=32] ; strengths: [B,H]
// out[b,h,m] = softmax_M( dot/(kn*mn+eps) * softplus(strength) )
// |cos|<1 -> v <= beta: softmax shifted by beta -> associative sum.
// One 2-CTA cluster per batch; each CTA does half the rows, posts 4 partial
// sums, cluster.sync (HW release/acquire, one IVALL), then normalizes its
// own half from L2-dirty lines. Single kernel, no chip-scope fences.

#define NB      256
#define MM      8192
#define WW      32
#define HH      4
#define EPSF    1e-5f
#define SEGS    2
#define NT1     256
#define ROWS_PER_CTA (MM / SEGS)                     // 4096
#define NWARPS  (NT1 / 32)                           // 8
#define ROWS_PER_WARP  (ROWS_PER_CTA / NWARPS)       // 512
#define ITERS   (ROWS_PER_WARP / 8)                  // 64 (8 rows / warp-iter)

__device__ float g_partial[NB * SEGS * HH];

// un-hoistable shared load: keeps key data out of the register file
__device__ __forceinline__ float4 lds128(uint32_t addr) {
    float4 v;
    asm volatile("ld.shared.v4.f32 {%0,%1,%2,%3}, [%4];"
        : "=f"(v.x), "=f"(v.y), "=f"(v.z), "=f"(v.w) : "r"(addr));
    return v;
}

__global__ __launch_bounds__(NT1, 6) __cluster_dims__(SEGS, 1, 1)
void weightfn_fused(const float* __restrict__ mem,
                    const float* __restrict__ keys,
                    const float* __restrict__ strengths,
                    float* __restrict__ out)
{
    __shared__ float4 sk4[HH][WW / 4];   // keys, [h][chunk]
    __shared__ float  skn[HH];
    __shared__ float  sbeta[HH];
    __shared__ float  sred[NWARPS][4];
    __shared__ float  sinv[HH];

    const int cta  = blockIdx.x;
    const int b    = cta >> 1;
    const int seg  = cta & 1;
    const int tid  = threadIdx.x;
    const int lane = tid & 31;
    const int wid  = tid >> 5;
    const int sub  = lane & 3;           // quarter of row / h index
    const int g    = lane >> 2;          // row within 8-row group

    if (tid < HH * WW)
        ((float*)sk4)[tid] = keys[b * HH * WW + tid];
    __syncthreads();
    if (tid < HH) {
        float s = strengths[b * HH + tid];
        sbeta[tid] = (s > 20.0f) ? s : log1pf(__expf(s));
        const float* k = (const float*)sk4[tid];
        float sq = 0.0f;
        #pragma unroll
        for (int w = 0; w < WW; w++) sq = fmaf(k[w], k[w], sq);
        skn[tid] = sqrtf(sq + EPSF);
    }
    __syncthreads();

    const float beta_h = sbeta[sub];
    const float kn_h   = skn[sub];

    const uint32_t skbase =
        (uint32_t)__cvta_generic_to_shared(&sk4[0][0]) + (uint32_t)(sub * 32);

    const float4* mp4 = (const float4*)mem + (size_t)b * MM * (WW / 4);
    float* ob = out + (size_t)b * HH * MM;

    const int warpRow0 = seg * ROWS_PER_CTA + wid * ROWS_PER_WARP;
    float lsum = 0.0f;

    #pragma unroll 4
    for (int i = 0; i < ITERS; i += 2) {
        const int rowA = warpRow0 + i * 8 + g;
        const int rowB = rowA + 8;
        // 4 LDG.128 front-batched (MLP 4)
        const float4 a0 = __ldcs(&mp4[rowA * 8 + sub * 2]);
        const float4 a1 = __ldcs(&mp4[rowA * 8 + sub * 2 + 1]);
        const float4 b0 = __ldcs(&mp4[rowB * 8 + sub * 2]);
        const float4 b1 = __ldcs(&mp4[rowB * 8 + sub * 2 + 1]);

        float sqA = fmaf(a0.x, a0.x, fmaf(a0.y, a0.y,
                    fmaf(a0.z, a0.z, fmaf(a0.w, a0.w, 0.0f))));
        sqA = fmaf(a1.x, a1.x, fmaf(a1.y, a1.y,
              fmaf(a1.z, a1.z, fmaf(a1.w, a1.w, sqA))));
        float sqB = fmaf(b0.x, b0.x, fmaf(b0.y, b0.y,
                    fmaf(b0.z, b0.z, fmaf(b0.w, b0.w, 0.0f))));
        sqB = fmaf(b1.x, b1.x, fmaf(b1.y, b1.y,
              fmaf(b1.z, b1.z, fmaf(b1.w, b1.w, sqB))));

        float dotA[HH], dotB[HH];
        #pragma unroll
        for (int h = 0; h < HH; h++) {
            const float4 k0 = lds128(skbase + (uint32_t)(h * 128));
            const float4 k1 = lds128(skbase + (uint32_t)(h * 128 + 16));
            float dA = fmaf(a0.x, k0.x, fmaf(a0.y, k0.y,
                       fmaf(a0.z, k0.z, fmaf(a0.w, k0.w, 0.0f))));
            dA = fmaf(a1.x, k1.x, fmaf(a1.y, k1.y,
                 fmaf(a1.z, k1.z, fmaf(a1.w, k1.w, dA))));
            float dB = fmaf(b0.x, k0.x, fmaf(b0.y, k0.y,
                       fmaf(b0.z, k0.z, fmaf(b0.w, k0.w, 0.0f))));
            dB = fmaf(b1.x, k1.x, fmaf(b1.y, k1.y,
                 fmaf(b1.z, k1.z, fmaf(b1.w, k1.w, dB))));
            dotA[h] = dA;
            dotB[h] = dB;
        }

        #pragma unroll
        for (int mask = 1; mask <= 2; mask <<= 1) {
            sqA += __shfl_xor_sync(0xffffffffu, sqA, mask);
            sqB += __shfl_xor_sync(0xffffffffu, sqB, mask);
            #pragma unroll
            for (int h = 0; h < HH; h++) {
                dotA[h] += __shfl_xor_sync(0xffffffffu, dotA[h], mask);
                dotB[h] += __shfl_xor_sync(0xffffffffu, dotB[h], mask);
            }
        }

        float dA = (sub == 0) ? dotA[0] : (sub == 1) ? dotA[1]
                 : (sub == 2) ? dotA[2] : dotA[3];
        float dB = (sub == 0) ? dotB[0] : (sub == 1) ? dotB[1]
                 : (sub == 2) ? dotB[2] : dotB[3];

        const float mnA = sqrtf(sqA + EPSF);
        const float mnB = sqrtf(sqB + EPSF);
        const float vA = dA * __fdividef(beta_h, fmaf(kn_h, mnA, EPSF));
        const float vB = dB * __fdividef(beta_h, fmaf(kn_h, mnB, EPSF));
        const float eA = __expf(vA - beta_h);
        const float eB = __expf(vB - beta_h);
        ob[sub * MM + rowA] = eA;
        ob[sub * MM + rowB] = eB;
        lsum += eA + eB;
    }

    // CTA-wide sum per h
    #pragma unroll
    for (int mask = 4; mask <= 16; mask <<= 1)
        lsum += __shfl_xor_sync(0xffffffffu, lsum, mask);
    if (lane < 4) sred[wid][lane] = lsum;
    __syncthreads();

    if (tid < 32) {
        float v = sred[tid >> 2][tid & 3];   // 8 warps x 4 h
        #pragma unroll
        for (int mask = 4; mask <= 16; mask <<= 1)
            v += __shfl_xor_sync(0xffffffffu, v, mask);
        if (tid < 4)
            g_partial[(b * SEGS + seg) * HH + tid] = v;
    }

    // cluster barrier: release our e-values + partials, acquire peer's.
    asm volatile("barrier.cluster.arrive.aligned;" ::: "memory");
    asm volatile("barrier.cluster.wait.aligned;"   ::: "memory");

    if (tid < HH) {
        // fixed order: seg0 + seg1 -> deterministic
        float s0 = __ldcg(&g_partial[(b * SEGS + 0) * HH + tid]);
        float s1 = __ldcg(&g_partial[(b * SEGS + 1) * HH + tid]);
        sinv[tid] = __fdividef(1.0f, s0 + s1);
    }
    __syncthreads();

    // normalize own half: for each h, 1024 float4; 256 thr -> 4 each (MLP 4)
    float4* o4 = (float4*)ob;
    #pragma unroll
    for (int h = 0; h < HH; h++) {
        const float inv = sinv[h];
        const int base = h * (MM / 4) + seg * (MM / 4 / 2);   // h*2048+seg*1024
        const int i0 = base + tid;
        const int i1 = base + tid + 256;
        const int i2 = base + tid + 512;
        const int i3 = base + tid + 768;
        float4 v0 = __ldcg(&o4[i0]);
        float4 v1 = __ldcg(&o4[i1]);
        float4 v2 = __ldcg(&o4[i2]);
        float4 v3 = __ldcg(&o4[i3]);
        v0.x *= inv; v0.y *= inv; v0.z *= inv; v0.w *= inv;
        v1.x *= inv; v1.y *= inv; v1.z *= inv; v1.w *= inv;
        v2.x *= inv; v2.y *= inv; v2.z *= inv; v2.w *= inv;
        v3.x *= inv; v3.y *= inv; v3.z *= inv; v3.w *= inv;
        __stcs(&o4[i0], v0);
        __stcs(&o4[i1], v1);
        __stcs(&o4[i2], v2);
        __stcs(&o4[i3], v3);
    }
}

extern "C" void kernel_launch(void* const* d_in, const int* in_sizes, int n_in,
                              void* d_out, int out_size)
{
    const float* mem       = (const float*)d_in[0];
    const float* keys      = (const float*)d_in[1];
    const float* strengths = (const float*)d_in[2];
    float* out             = (float*)d_out;

    weightfn_fused<<<NB * SEGS, NT1>>>(mem, keys, strengths, out);
}